// round 2
// baseline (speedup 1.0000x reference)
#include <cuda_runtime.h>
#include <math.h>

// ---------------------------------------------------------------------------
// SparseMoeBlock: N=8192 tokens, D=2048 hidden, E=16 experts, top-2, I=1408
// inputs: hidden_states f32[4,2048,2048], gate_w f32[16,2048],
//         wg f32[16,2048,1408], wu f32[16,2048,1408], wd f32[16,1408,2048]
// output: f32[4,2048,2048]
// ---------------------------------------------------------------------------

#define DHID  2048
#define NEXP  16
#define INTER 1408
#define NTOK  8192
#define NASSIGN (NTOK * 2)

#define BM 64
#define BN 64
#define KT 16

// device scratch (allocation-free contract: __device__ globals)
__device__ int   g_cnt[NEXP];
__device__ int   g_off[NEXP + 1];
__device__ int   g_tok[NEXP][NTOK];
__device__ float g_wt[NEXP][NTOK];
__device__ float g_h[(size_t)NASSIGN * INTER];   // 92.3 MB intermediate h

// ---------------------------------------------------------------------------
// 0. zero output + expert counters
// ---------------------------------------------------------------------------
__global__ void zero_kernel(float* __restrict__ out, int n) {
    int i = blockIdx.x * blockDim.x + threadIdx.x;
    int stride = gridDim.x * blockDim.x;
    for (; i < n; i += stride) out[i] = 0.0f;
    if (blockIdx.x == 0 && threadIdx.x < NEXP) g_cnt[threadIdx.x] = 0;
}

// ---------------------------------------------------------------------------
// 1. router: one warp per token. logits -> top2 -> renormalized softmax pair.
//    w1 = 1/(1+exp(l2-l1)), w2 = 1-w1  (exactly the reference's renorm math)
// ---------------------------------------------------------------------------
__global__ __launch_bounds__(256) void router_kernel(
    const float* __restrict__ x, const float* __restrict__ gw) {
    int gwarp = (blockIdx.x * blockDim.x + threadIdx.x) >> 5;
    int lane  = threadIdx.x & 31;
    if (gwarp >= NTOK) return;
    const float* xr = x + (size_t)gwarp * DHID;

    float acc[NEXP];
#pragma unroll
    for (int e = 0; e < NEXP; ++e) acc[e] = 0.0f;

    for (int d = lane; d < DHID; d += 32) {
        float xv = xr[d];
#pragma unroll
        for (int e = 0; e < NEXP; ++e) acc[e] += xv * gw[e * DHID + d];
    }
#pragma unroll
    for (int e = 0; e < NEXP; ++e) {
#pragma unroll
        for (int s = 16; s > 0; s >>= 1)
            acc[e] += __shfl_xor_sync(0xffffffffu, acc[e], s);
    }
    if (lane == 0) {
        // top-2 (stable: first index wins ties, matching lax.top_k)
        float m1 = acc[0]; int a1 = 0;
#pragma unroll
        for (int e = 1; e < NEXP; ++e)
            if (acc[e] > m1) { m1 = acc[e]; a1 = e; }
        float m2 = -INFINITY; int a2 = 0;
#pragma unroll
        for (int e = 0; e < NEXP; ++e)
            if (e != a1 && acc[e] > m2) { m2 = acc[e]; a2 = e; }

        float p2 = expf(m2 - m1);
        float w1 = 1.0f / (1.0f + p2);
        float w2 = 1.0f - w1;

        int i1 = atomicAdd(&g_cnt[a1], 1);
        g_tok[a1][i1] = gwarp; g_wt[a1][i1] = w1;
        int i2 = atomicAdd(&g_cnt[a2], 1);
        g_tok[a2][i2] = gwarp; g_wt[a2][i2] = w2;
    }
}

// ---------------------------------------------------------------------------
// 2. exclusive prefix sum over the 16 counts
// ---------------------------------------------------------------------------
__global__ void offsets_kernel() {
    if (threadIdx.x == 0) {
        int o = 0;
        for (int e = 0; e < NEXP; ++e) { g_off[e] = o; o += g_cnt[e]; }
        g_off[NEXP] = o;
    }
}

// ---------------------------------------------------------------------------
// 3. GEMM1: gathered X [rows x 2048] @ {wg_e, wu_e} [2048 x 1408],
//    h = silu(g)*u written to g_h. Tile 64x64, KT=16, 256 thr, 4x4x2 per thr.
// ---------------------------------------------------------------------------
__global__ __launch_bounds__(256) void gemm1_kernel(
    const float* __restrict__ x,
    const float* __restrict__ wg,
    const float* __restrict__ wu) {
    int e   = blockIdx.z;
    int cnt = g_cnt[e];
    int m0  = blockIdx.y * BM;
    if (m0 >= cnt) return;
    int n0   = blockIdx.x * BN;
    int base = g_off[e];

    __shared__ float As[KT][68];         // padded: transposed A tile
    __shared__ float Bg[KT][BN];
    __shared__ float Bu[KT][BN];

    int tid = threadIdx.x;
    int tx = tid & 15, ty = tid >> 4;

    // A-load assignment: thread -> (row lm, k-chunk lk4)
    int lm  = tid >> 2;
    int lk4 = (tid & 3) * 4;
    const float* xrow = nullptr;
    if (m0 + lm < cnt) xrow = x + (size_t)g_tok[e][m0 + lm] * DHID;

    // B-load assignment
    int bk  = tid >> 4;
    int bn4 = (tid & 15) * 4;
    const float* wge = wg + (size_t)e * DHID * INTER + n0 + bn4;
    const float* wue = wu + (size_t)e * DHID * INTER + n0 + bn4;

    float accg[4][4], accu[4][4];
#pragma unroll
    for (int i = 0; i < 4; ++i)
#pragma unroll
        for (int j = 0; j < 4; ++j) { accg[i][j] = 0.0f; accu[i][j] = 0.0f; }

    for (int k0 = 0; k0 < DHID; k0 += KT) {
        float4 av = make_float4(0.f, 0.f, 0.f, 0.f);
        if (xrow) av = *(const float4*)(xrow + k0 + lk4);
        float4 bgv = *(const float4*)(wge + (size_t)(k0 + bk) * INTER);
        float4 buv = *(const float4*)(wue + (size_t)(k0 + bk) * INTER);

        __syncthreads();
        As[lk4 + 0][lm] = av.x;
        As[lk4 + 1][lm] = av.y;
        As[lk4 + 2][lm] = av.z;
        As[lk4 + 3][lm] = av.w;
        *(float4*)&Bg[bk][bn4] = bgv;
        *(float4*)&Bu[bk][bn4] = buv;
        __syncthreads();

#pragma unroll
        for (int k = 0; k < KT; ++k) {
            float4 a  = *(const float4*)&As[k][ty * 4];
            float4 bg = *(const float4*)&Bg[k][tx * 4];
            float4 bu = *(const float4*)&Bu[k][tx * 4];
            float af[4] = {a.x, a.y, a.z, a.w};
            float gf[4] = {bg.x, bg.y, bg.z, bg.w};
            float uf[4] = {bu.x, bu.y, bu.z, bu.w};
#pragma unroll
            for (int i = 0; i < 4; ++i)
#pragma unroll
                for (int j = 0; j < 4; ++j) {
                    accg[i][j] += af[i] * gf[j];
                    accu[i][j] += af[i] * uf[j];
                }
        }
    }

    // epilogue: h = silu(g) * u
#pragma unroll
    for (int i = 0; i < 4; ++i) {
        int m = m0 + ty * 4 + i;
        if (m < cnt) {
            float* hrow = g_h + (size_t)(base + m) * INTER + n0 + tx * 4;
            float4 hv;
            float g0 = accg[i][0], g1 = accg[i][1], g2 = accg[i][2], g3 = accg[i][3];
            hv.x = (g0 / (1.0f + expf(-g0))) * accu[i][0];
            hv.y = (g1 / (1.0f + expf(-g1))) * accu[i][1];
            hv.z = (g2 / (1.0f + expf(-g2))) * accu[i][2];
            hv.w = (g3 / (1.0f + expf(-g3))) * accu[i][3];
            *(float4*)hrow = hv;
        }
    }
}

// ---------------------------------------------------------------------------
// 4. GEMM2: h [rows x 1408] @ wd_e [1408 x 2048], scaled atomic scatter to out
// ---------------------------------------------------------------------------
__global__ __launch_bounds__(256) void gemm2_kernel(
    const float* __restrict__ wd, float* __restrict__ out) {
    int e   = blockIdx.z;
    int cnt = g_cnt[e];
    int m0  = blockIdx.y * BM;
    if (m0 >= cnt) return;
    int n0   = blockIdx.x * BN;
    int base = g_off[e];

    __shared__ float As[KT][68];
    __shared__ float Bs[KT][BN];

    int tid = threadIdx.x;
    int tx = tid & 15, ty = tid >> 4;

    int lm  = tid >> 2;
    int lk4 = (tid & 3) * 4;
    const float* hrow = nullptr;
    if (m0 + lm < cnt) hrow = g_h + (size_t)(base + m0 + lm) * INTER;

    int bk  = tid >> 4;
    int bn4 = (tid & 15) * 4;
    const float* wde = wd + (size_t)e * INTER * DHID + n0 + bn4;

    float acc[4][4];
#pragma unroll
    for (int i = 0; i < 4; ++i)
#pragma unroll
        for (int j = 0; j < 4; ++j) acc[i][j] = 0.0f;

    for (int k0 = 0; k0 < INTER; k0 += KT) {
        float4 av = make_float4(0.f, 0.f, 0.f, 0.f);
        if (hrow) av = *(const float4*)(hrow + k0 + lk4);
        float4 bv = *(const float4*)(wde + (size_t)(k0 + bk) * DHID);

        __syncthreads();
        As[lk4 + 0][lm] = av.x;
        As[lk4 + 1][lm] = av.y;
        As[lk4 + 2][lm] = av.z;
        As[lk4 + 3][lm] = av.w;
        *(float4*)&Bs[bk][bn4] = bv;
        __syncthreads();

#pragma unroll
        for (int k = 0; k < KT; ++k) {
            float4 a = *(const float4*)&As[k][ty * 4];
            float4 b = *(const float4*)&Bs[k][tx * 4];
            float af[4] = {a.x, a.y, a.z, a.w};
            float bf[4] = {b.x, b.y, b.z, b.w};
#pragma unroll
            for (int i = 0; i < 4; ++i)
#pragma unroll
                for (int j = 0; j < 4; ++j)
                    acc[i][j] += af[i] * bf[j];
        }
    }

    // epilogue: out[token] += w * y  (atomic; 2 adds/element, fp32 add commutes)
#pragma unroll
    for (int i = 0; i < 4; ++i) {
        int m = m0 + ty * 4 + i;
        if (m < cnt) {
            int tok  = g_tok[e][m];
            float w  = g_wt[e][m];
            float* orow = out + (size_t)tok * DHID + n0 + tx * 4;
#pragma unroll
            for (int j = 0; j < 4; ++j)
                atomicAdd(&orow[j], w * acc[i][j]);
        }
    }
}

// ---------------------------------------------------------------------------
extern "C" void kernel_launch(void* const* d_in, const int* in_sizes, int n_in,
                              void* d_out, int out_size) {
    const float* x  = (const float*)d_in[0];
    const float* gw = (const float*)d_in[1];
    const float* wg = (const float*)d_in[2];
    const float* wu = (const float*)d_in[3];
    const float* wd = (const float*)d_in[4];
    float* out = (float*)d_out;

    zero_kernel<<<2048, 256>>>(out, NTOK * DHID);
    router_kernel<<<NTOK / 8, 256>>>(x, gw);
    offsets_kernel<<<1, 32>>>();
    gemm1_kernel<<<dim3(INTER / BN, NTOK / BM, NEXP), 256>>>(x, wg, wu);
    gemm2_kernel<<<dim3(DHID / BN, NTOK / BM, NEXP), 256>>>(wd, out);
}

// round 8
// speedup vs baseline: 3.1096x; 3.1096x over previous
#include <cuda_runtime.h>
#include <cuda_bf16.h>
#include <stdint.h>
#include <math.h>

// ===========================================================================
// SparseMoeBlock via warp-level bf16 mma.sync (sm_80-portable PTX) with
// 3-term hi/lo split for fp32-grade accuracy. tcgen05 unavailable (toolchain
// targets compute_103 without the 'a' feature set).
// ===========================================================================

#define DHID  2048
#define NEXP  16
#define INTER 1408
#define NTOK  8192
#define NASSIGN (NTOK * 2)

#define KS       32            // K elems per stage
#define ASTRIDE  40            // smem row stride in bf16 elems (80B) - conflict-free ldmatrix
#define NBUF     3

// gemm1 smem plane offsets (bytes, per stage)
#define G1_AH 0
#define G1_AL 10240
#define G1_GH 20480
#define G1_GL 25600
#define G1_UH 30720
#define G1_UL 35840
#define G1_STAGE 40960

// gemm2 smem plane offsets
#define G2_AH 0
#define G2_AL 10240
#define G2_BH 20480
#define G2_BL 30720
#define G2_STAGE 40960

#define SMEM_DYN (NBUF * 40960 + 128)

// ---------------------------------------------------------------------------
// PTX helpers
// ---------------------------------------------------------------------------
__device__ __forceinline__ uint32_t smem_u32(const void* p) {
    uint32_t a;
    asm("{ .reg .u64 t; cvta.to.shared.u64 t, %1; cvt.u32.u64 %0, t; }" : "=r"(a) : "l"(p));
    return a;
}

#define CP16(dst, src, sz) \
    asm volatile("cp.async.cg.shared.global [%0], [%1], 16, %2;" \
                 :: "r"(dst), "l"(src), "r"(sz))
#define CP_COMMIT() asm volatile("cp.async.commit_group;" ::: "memory")
#define CP_WAIT2()  asm volatile("cp.async.wait_group 2;" ::: "memory")

#define LDSM4(r0, r1, r2, r3, addr) \
    asm volatile("ldmatrix.sync.aligned.m8n8.x4.shared.b16 {%0,%1,%2,%3}, [%4];" \
                 : "=r"(r0), "=r"(r1), "=r"(r2), "=r"(r3) : "r"(addr))

#define MMA(d, a, b0, b1) \
    asm volatile("mma.sync.aligned.m16n8k16.row.col.f32.bf16.bf16.f32 " \
                 "{%0,%1,%2,%3}, {%4,%5,%6,%7}, {%8,%9}, {%0,%1,%2,%3};" \
                 : "+f"((d)[0]), "+f"((d)[1]), "+f"((d)[2]), "+f"((d)[3]) \
                 : "r"((a)[0]), "r"((a)[1]), "r"((a)[2]), "r"((a)[3]), \
                   "r"(b0), "r"(b1))

__device__ __forceinline__ uint32_t bf2u(__nv_bfloat16 a, __nv_bfloat16 b) {
    __nv_bfloat162 t(a, b);
    return *reinterpret_cast<uint32_t*>(&t);
}
__device__ __forceinline__ void split1(float x, __nv_bfloat16& h, __nv_bfloat16& l) {
    h = __float2bfloat16(x);
    l = __float2bfloat16(x - __bfloat162float(h));
}
__device__ __forceinline__ float silu(float g) {
    return g / (1.0f + expf(-g));
}

// ---------------------------------------------------------------------------
// device scratch
// ---------------------------------------------------------------------------
#define WELEMS (16ull * 2048 * 1408)
__device__ int   g_cnt[NEXP];
__device__ int   g_off[NEXP + 1];
__device__ int   g_tok[NEXP][NTOK];
__device__ float g_wt[NEXP][NTOK];
__device__ __nv_bfloat16 g_x_hi[(size_t)NTOK * DHID], g_x_lo[(size_t)NTOK * DHID];
__device__ __nv_bfloat16 g_wgT_hi[WELEMS], g_wgT_lo[WELEMS];   // [e][n(1408)][k(2048)]
__device__ __nv_bfloat16 g_wuT_hi[WELEMS], g_wuT_lo[WELEMS];
__device__ __nv_bfloat16 g_wdT_hi[WELEMS], g_wdT_lo[WELEMS];   // [e][n(2048)][k(1408)]
__device__ __nv_bfloat16 g_h_hi[(size_t)NASSIGN * INTER], g_h_lo[(size_t)NASSIGN * INTER];

// ---------------------------------------------------------------------------
// 0. zero output + counters
// ---------------------------------------------------------------------------
__global__ void zero_kernel(float* __restrict__ out, int n) {
    int i = blockIdx.x * blockDim.x + threadIdx.x;
    int stride = gridDim.x * blockDim.x;
    for (; i < n; i += stride) out[i] = 0.0f;
    if (blockIdx.x == 0 && threadIdx.x < NEXP) g_cnt[threadIdx.x] = 0;
}

// ---------------------------------------------------------------------------
// 1. router
// ---------------------------------------------------------------------------
__global__ __launch_bounds__(256) void router_kernel(
    const float* __restrict__ x, const float* __restrict__ gw) {
    int gwarp = (blockIdx.x * blockDim.x + threadIdx.x) >> 5;
    int lane  = threadIdx.x & 31;
    if (gwarp >= NTOK) return;
    const float* xr = x + (size_t)gwarp * DHID;

    float acc[NEXP];
#pragma unroll
    for (int e = 0; e < NEXP; ++e) acc[e] = 0.0f;
    for (int d = lane; d < DHID; d += 32) {
        float xv = xr[d];
#pragma unroll
        for (int e = 0; e < NEXP; ++e) acc[e] += xv * gw[e * DHID + d];
    }
#pragma unroll
    for (int e = 0; e < NEXP; ++e)
#pragma unroll
        for (int s = 16; s > 0; s >>= 1)
            acc[e] += __shfl_xor_sync(0xffffffffu, acc[e], s);
    if (lane == 0) {
        float m1 = acc[0]; int a1 = 0;
#pragma unroll
        for (int e = 1; e < NEXP; ++e)
            if (acc[e] > m1) { m1 = acc[e]; a1 = e; }
        float m2 = -INFINITY; int a2 = 0;
#pragma unroll
        for (int e = 0; e < NEXP; ++e)
            if (e != a1 && acc[e] > m2) { m2 = acc[e]; a2 = e; }
        float w1 = 1.0f / (1.0f + expf(m2 - m1));
        float w2 = 1.0f - w1;
        int i1 = atomicAdd(&g_cnt[a1], 1);
        g_tok[a1][i1] = gwarp; g_wt[a1][i1] = w1;
        int i2 = atomicAdd(&g_cnt[a2], 1);
        g_tok[a2][i2] = gwarp; g_wt[a2][i2] = w2;
    }
}

__global__ void offsets_kernel() {
    if (threadIdx.x == 0) {
        int o = 0;
        for (int e = 0; e < NEXP; ++e) { g_off[e] = o; o += g_cnt[e]; }
        g_off[NEXP] = o;
    }
}

// ---------------------------------------------------------------------------
// 2a. split x fp32 -> bf16 hi/lo planes
// ---------------------------------------------------------------------------
__global__ __launch_bounds__(256) void split_x_kernel(const float* __restrict__ x) {
    size_t i = ((size_t)blockIdx.x * blockDim.x + threadIdx.x) * 4;
    if (i >= (size_t)NTOK * DHID) return;
    float4 v = *(const float4*)(x + i);
    __nv_bfloat16 h0, h1, h2, h3, l0, l1, l2, l3;
    split1(v.x, h0, l0); split1(v.y, h1, l1);
    split1(v.z, h2, l2); split1(v.w, h3, l3);
    *(uint2*)(g_x_hi + i) = make_uint2(bf2u(h0, h1), bf2u(h2, h3));
    *(uint2*)(g_x_lo + i) = make_uint2(bf2u(l0, l1), bf2u(l2, l3));
}

// ---------------------------------------------------------------------------
// 2b. transpose [K,N] -> [N,K] per expert + fp32 -> bf16 hi/lo split
// ---------------------------------------------------------------------------
__global__ __launch_bounds__(256) void transpose_split_kernel(
    const float* __restrict__ in, int which, int K, int N) {
    __shared__ float t[32][33];
    int e = blockIdx.z;
    const float* ine = in + (size_t)e * K * N;
    __nv_bfloat16* ohi = (which == 0) ? g_wgT_hi : (which == 1) ? g_wuT_hi : g_wdT_hi;
    __nv_bfloat16* olo = (which == 0) ? g_wgT_lo : (which == 1) ? g_wuT_lo : g_wdT_lo;
    size_t ob = (size_t)e * K * N;
    int n0 = blockIdx.x * 32, k0 = blockIdx.y * 32;
    int tx = threadIdx.x, ty = threadIdx.y;    // 32 x 8
#pragma unroll
    for (int j = 0; j < 4; ++j)
        t[ty + j * 8][tx] = ine[(size_t)(k0 + ty + j * 8) * N + n0 + tx];
    __syncthreads();
#pragma unroll
    for (int j = 0; j < 4; ++j) {
        int n = n0 + ty + j * 8, k = k0 + tx;
        float v = t[tx][ty + j * 8];
        __nv_bfloat16 h, l; split1(v, h, l);
        ohi[ob + (size_t)n * K + k] = h;
        olo[ob + (size_t)n * K + k] = l;
    }
}

// ---------------------------------------------------------------------------
// 3. GEMM1: CTA 128(m) x 64(n), computes gate AND up, K=2048.
//    8 warps (4m x 2n), warp tile 32x32 per matrix. 3-term bf16 mma.
//    Epilogue: h = silu(g)*u -> bf16 hi/lo planes.
// ---------------------------------------------------------------------------
__global__ __launch_bounds__(256) void gemm1_mma(void) {
    int e   = blockIdx.z;
    int cnt = g_cnt[e];
    int m0  = blockIdx.y * 128;
    if (m0 >= cnt) return;
    int n0   = blockIdx.x * 64;
    int base = g_off[e];

    extern __shared__ char dynsm[];
    uint32_t raw = smem_u32(dynsm);
    uint32_t smA = (raw + 127u) & ~127u;

    int tid = threadIdx.x, wid = tid >> 5, lane = tid & 31;

    // ---- producer mapping ----
    // A: 128 rows, 2 threads/row, each 2 x 16B chunks per plane
    int arow = tid >> 1;
    int aco  = (tid & 1) * 16;                 // elem offset within 32
    bool avalid = (m0 + arow < cnt);
    int atok = avalid ? g_tok[e][m0 + arow] : 0;
    uint32_t asz = avalid ? 16u : 0u;
    const __nv_bfloat16* axh = g_x_hi + (size_t)atok * DHID + aco;
    const __nv_bfloat16* axl = g_x_lo + (size_t)atok * DHID + aco;
    uint32_t adsth = arow * 80 + aco * 2;      // byte offset in A plane

    // B: 64 rows, 4 threads/row, 1 x 16B chunk per (mat,plane)
    int brow = tid >> 2;
    int bco  = (tid & 3) * 8;
    size_t wbase = ((size_t)e * INTER + n0 + brow) * DHID + bco;
    const __nv_bfloat16* bsrc[4] = { g_wgT_hi + wbase, g_wgT_lo + wbase,
                                     g_wuT_hi + wbase, g_wuT_lo + wbase };
    const uint32_t bpo[4] = { G1_GH, G1_GL, G1_UH, G1_UL };
    uint32_t bdst = brow * 80 + bco * 2;

    // ---- consumer mapping ----
    int wm = (wid >> 1) * 32;
    int wn = (wid & 1) * 32;
    int arl = lane & 15;                       // ldmatrix A row lane
    int acl = (lane >> 4) * 8;                 // ldmatrix A col lane
    int bnl = (lane & 7) + ((lane >> 4) << 3); // ldmatrix B n lane
    int bkl = ((lane >> 3) & 1) * 8;           // ldmatrix B k lane

    float gacc[2][4][4], uacc[2][4][4];
#pragma unroll
    for (int mb = 0; mb < 2; ++mb)
#pragma unroll
        for (int nb = 0; nb < 4; ++nb)
#pragma unroll
            for (int i = 0; i < 4; ++i) { gacc[mb][nb][i] = 0.f; uacc[mb][nb][i] = 0.f; }

    const int NST = DHID / KS;   // 64

    // issue one stage's cp.async
    auto issue = [&](int s) {
        uint32_t st = smA + (s % NBUF) * G1_STAGE;
        int k0 = s * KS;
        CP16(st + G1_AH + adsth,      axh + k0,     asz);
        CP16(st + G1_AH + adsth + 16, axh + k0 + 8, asz);
        CP16(st + G1_AL + adsth,      axl + k0,     asz);
        CP16(st + G1_AL + adsth + 16, axl + k0 + 8, asz);
#pragma unroll
        for (int mp = 0; mp < 4; ++mp)
            CP16(st + bpo[mp] + bdst, bsrc[mp] + k0, 16u);
    };

    issue(0); CP_COMMIT();
    issue(1); CP_COMMIT();

    for (int s = 0; s < NST; ++s) {
        if (s + 2 < NST) issue(s + 2);
        CP_COMMIT();
        CP_WAIT2();
        __syncthreads();

        uint32_t st = smA + (s % NBUF) * G1_STAGE;
#pragma unroll
        for (int kk = 0; kk < 2; ++kk) {
            int kofs = kk * 16;
            uint32_t ah[2][4], al[2][4];
#pragma unroll
            for (int mb = 0; mb < 2; ++mb) {
                uint32_t ao = ((wm + mb * 16 + arl) * ASTRIDE + kofs + acl) * 2;
                LDSM4(ah[mb][0], ah[mb][1], ah[mb][2], ah[mb][3], st + G1_AH + ao);
                LDSM4(al[mb][0], al[mb][1], al[mb][2], al[mb][3], st + G1_AL + ao);
            }
            uint32_t bgh[2][4], bgl[2][4], buh[2][4], bul[2][4];
#pragma unroll
            for (int p = 0; p < 2; ++p) {
                uint32_t bo = ((wn + p * 16 + bnl) * ASTRIDE + kofs + bkl) * 2;
                LDSM4(bgh[p][0], bgh[p][1], bgh[p][2], bgh[p][3], st + G1_GH + bo);
                LDSM4(bgl[p][0], bgl[p][1], bgl[p][2], bgl[p][3], st + G1_GL + bo);
                LDSM4(buh[p][0], buh[p][1], buh[p][2], buh[p][3], st + G1_UH + bo);
                LDSM4(bul[p][0], bul[p][1], bul[p][2], bul[p][3], st + G1_UL + bo);
            }
#pragma unroll
            for (int mb = 0; mb < 2; ++mb)
#pragma unroll
                for (int nb = 0; nb < 4; ++nb) {
                    int p = nb >> 1, o = (nb & 1) * 2;
                    MMA(gacc[mb][nb], ah[mb], bgh[p][o], bgh[p][o + 1]);
                    MMA(gacc[mb][nb], ah[mb], bgl[p][o], bgl[p][o + 1]);
                    MMA(gacc[mb][nb], al[mb], bgh[p][o], bgh[p][o + 1]);
                    MMA(uacc[mb][nb], ah[mb], buh[p][o], buh[p][o + 1]);
                    MMA(uacc[mb][nb], ah[mb], bul[p][o], bul[p][o + 1]);
                    MMA(uacc[mb][nb], al[mb], buh[p][o], buh[p][o + 1]);
                }
        }
        __syncthreads();
    }

    // epilogue: h = silu(g)*u, split to bf16 hi/lo
#pragma unroll
    for (int mb = 0; mb < 2; ++mb) {
#pragma unroll
        for (int half = 0; half < 2; ++half) {
            int m = m0 + wm + mb * 16 + (lane >> 2) + half * 8;
            if (m < cnt) {
                __nv_bfloat16* hh = g_h_hi + (size_t)(base + m) * INTER + n0;
                __nv_bfloat16* hl = g_h_lo + (size_t)(base + m) * INTER + n0;
#pragma unroll
                for (int nb = 0; nb < 4; ++nb) {
                    int c = wn + nb * 8 + (lane & 3) * 2;
                    float g0 = gacc[mb][nb][half * 2],     g1 = gacc[mb][nb][half * 2 + 1];
                    float u0 = uacc[mb][nb][half * 2],     u1 = uacc[mb][nb][half * 2 + 1];
                    float h0 = silu(g0) * u0, h1 = silu(g1) * u1;
                    __nv_bfloat16 a0, b0, a1, b1;
                    split1(h0, a0, b0); split1(h1, a1, b1);
                    *(uint32_t*)(hh + c) = bf2u(a0, a1);
                    *(uint32_t*)(hl + c) = bf2u(b0, b1);
                }
            }
        }
    }
}

// ---------------------------------------------------------------------------
// 4. GEMM2: CTA 128(m) x 128(n), K=1408. 8 warps (2m x 4n), warp tile 64x32.
//    Weighted atomicAdd scatter to out.
// ---------------------------------------------------------------------------
__global__ __launch_bounds__(256) void gemm2_mma(float* __restrict__ out) {
    int e   = blockIdx.z;
    int cnt = g_cnt[e];
    int m0  = blockIdx.y * 128;
    if (m0 >= cnt) return;
    int n0   = blockIdx.x * 128;
    int base = g_off[e];

    extern __shared__ char dynsm[];
    uint32_t raw = smem_u32(dynsm);
    uint32_t smA = (raw + 127u) & ~127u;

    int tid = threadIdx.x, wid = tid >> 5, lane = tid & 31;

    // producers: A 128 rows (2 thr/row, 2 chunks per plane); B 128 rows same
    int arow = tid >> 1;
    int aco  = (tid & 1) * 16;
    bool avalid = (m0 + arow < cnt);
    uint32_t asz = avalid ? 16u : 0u;
    size_t arix = (size_t)(base + (avalid ? m0 + arow : 0)) * INTER + aco;
    const __nv_bfloat16* ahp = g_h_hi + arix;
    const __nv_bfloat16* alp = g_h_lo + arix;
    uint32_t adst = arow * 80 + aco * 2;

    size_t wbase = ((size_t)e * DHID + n0 + arow) * INTER + aco;
    const __nv_bfloat16* bhp = g_wdT_hi + wbase;
    const __nv_bfloat16* blp = g_wdT_lo + wbase;

    // consumers
    int wm = (wid & 1) * 64;
    int wn = (wid >> 1) * 32;
    int arl = lane & 15, acl = (lane >> 4) * 8;
    int bnl = (lane & 7) + ((lane >> 4) << 3);
    int bkl = ((lane >> 3) & 1) * 8;

    float acc[4][4][4];
#pragma unroll
    for (int mb = 0; mb < 4; ++mb)
#pragma unroll
        for (int nb = 0; nb < 4; ++nb)
#pragma unroll
            for (int i = 0; i < 4; ++i) acc[mb][nb][i] = 0.f;

    const int NST = INTER / KS;  // 44

    auto issue = [&](int s) {
        uint32_t st = smA + (s % NBUF) * G2_STAGE;
        int k0 = s * KS;
        CP16(st + G2_AH + adst,      ahp + k0,     asz);
        CP16(st + G2_AH + adst + 16, ahp + k0 + 8, asz);
        CP16(st + G2_AL + adst,      alp + k0,     asz);
        CP16(st + G2_AL + adst + 16, alp + k0 + 8, asz);
        CP16(st + G2_BH + adst,      bhp + k0,     16u);
        CP16(st + G2_BH + adst + 16, bhp + k0 + 8, 16u);
        CP16(st + G2_BL + adst,      blp + k0,     16u);
        CP16(st + G2_BL + adst + 16, blp + k0 + 8, 16u);
    };

    issue(0); CP_COMMIT();
    issue(1); CP_COMMIT();

    for (int s = 0; s < NST; ++s) {
        if (s + 2 < NST) issue(s + 2);
        CP_COMMIT();
        CP_WAIT2();
        __syncthreads();

        uint32_t st = smA + (s % NBUF) * G2_STAGE;
#pragma unroll
        for (int kk = 0; kk < 2; ++kk) {
            int kofs = kk * 16;
            uint32_t ah[4][4], al[4][4];
#pragma unroll
            for (int mb = 0; mb < 4; ++mb) {
                uint32_t ao = ((wm + mb * 16 + arl) * ASTRIDE + kofs + acl) * 2;
                LDSM4(ah[mb][0], ah[mb][1], ah[mb][2], ah[mb][3], st + G2_AH + ao);
                LDSM4(al[mb][0], al[mb][1], al[mb][2], al[mb][3], st + G2_AL + ao);
            }
            uint32_t bh[2][4], bl[2][4];
#pragma unroll
            for (int p = 0; p < 2; ++p) {
                uint32_t bo = ((wn + p * 16 + bnl) * ASTRIDE + kofs + bkl) * 2;
                LDSM4(bh[p][0], bh[p][1], bh[p][2], bh[p][3], st + G2_BH + bo);
                LDSM4(bl[p][0], bl[p][1], bl[p][2], bl[p][3], st + G2_BL + bo);
            }
#pragma unroll
            for (int mb = 0; mb < 4; ++mb)
#pragma unroll
                for (int nb = 0; nb < 4; ++nb) {
                    int p = nb >> 1, o = (nb & 1) * 2;
                    MMA(acc[mb][nb], ah[mb], bh[p][o], bh[p][o + 1]);
                    MMA(acc[mb][nb], ah[mb], bl[p][o], bl[p][o + 1]);
                    MMA(acc[mb][nb], al[mb], bh[p][o], bh[p][o + 1]);
                }
        }
        __syncthreads();
    }

    // epilogue: weighted atomic scatter
#pragma unroll
    for (int mb = 0; mb < 4; ++mb) {
#pragma unroll
        for (int half = 0; half < 2; ++half) {
            int m = m0 + wm + mb * 16 + (lane >> 2) + half * 8;
            if (m < cnt) {
                int tok  = g_tok[e][m];
                float w  = g_wt[e][m];
                float* orow = out + (size_t)tok * DHID + n0;
#pragma unroll
                for (int nb = 0; nb < 4; ++nb) {
                    int c = wn + nb * 8 + (lane & 3) * 2;
                    atomicAdd(&orow[c],     w * acc[mb][nb][half * 2]);
                    atomicAdd(&orow[c + 1], w * acc[mb][nb][half * 2 + 1]);
                }
            }
        }
    }
}

// ---------------------------------------------------------------------------
extern "C" void kernel_launch(void* const* d_in, const int* in_sizes, int n_in,
                              void* d_out, int out_size) {
    const float* x  = (const float*)d_in[0];
    const float* gw = (const float*)d_in[1];
    const float* wg = (const float*)d_in[2];
    const float* wu = (const float*)d_in[3];
    const float* wd = (const float*)d_in[4];
    float* out = (float*)d_out;

    cudaFuncSetAttribute(gemm1_mma, cudaFuncAttributeMaxDynamicSharedMemorySize, SMEM_DYN);
    cudaFuncSetAttribute(gemm2_mma, cudaFuncAttributeMaxDynamicSharedMemorySize, SMEM_DYN);

    zero_kernel<<<2048, 256>>>(out, NTOK * DHID);
    router_kernel<<<NTOK / 8, 256>>>(x, gw);
    offsets_kernel<<<1, 32>>>();
    split_x_kernel<<<(NTOK * DHID / 4 + 255) / 256, 256>>>(x);
    transpose_split_kernel<<<dim3(INTER / 32, DHID / 32, NEXP), dim3(32, 8)>>>(wg, 0, DHID, INTER);
    transpose_split_kernel<<<dim3(INTER / 32, DHID / 32, NEXP), dim3(32, 8)>>>(wu, 1, DHID, INTER);
    transpose_split_kernel<<<dim3(DHID / 32, INTER / 32, NEXP), dim3(32, 8)>>>(wd, 2, INTER, DHID);
    gemm1_mma<<<dim3(INTER / 64, NTOK / 128, NEXP), 256, SMEM_DYN>>>();
    gemm2_mma<<<dim3(DHID / 128, NTOK / 128, NEXP), 256, SMEM_DYN>>>(out);
}

// round 9
// speedup vs baseline: 3.2659x; 1.0503x over previous
#include <cuda_runtime.h>
#include <cuda_fp16.h>
#include <stdint.h>
#include <math.h>

// ===========================================================================
// SparseMoeBlock via warp-level fp16 mma.sync with 2-term split:
//   A (activations) = Ah + Al  (fp16 pair, exact to ~2^-24)
//   B (weights)     = fp16 single (2^-12 rounding, random sign)
// Per-GEMM rel err ~2.4e-4, end-to-end ~5e-4 < 1e-3 tolerance.
// ===========================================================================

#define DHID  2048
#define NEXP  16
#define INTER 1408
#define NTOK  8192
#define NASSIGN (NTOK * 2)

#define KS       32            // K elems per stage
#define ASTRIDE  40            // smem row stride in fp16 elems (80B) - conflict-free ldmatrix
#define NBUF     3

// gemm1 smem plane offsets (bytes, per stage): Ah, Al (128rowsx80B), G, U (64rowsx80B)
#define G1_AH 0
#define G1_AL 10240
#define G1_G  20480
#define G1_U  25600
#define G1_STAGE 30720

// gemm2: Ah, Al (128x80B), B (128x80B)
#define G2_AH 0
#define G2_AL 10240
#define G2_B  20480
#define G2_STAGE 30720

#define SMEM_DYN (NBUF * 30720 + 128)

// ---------------------------------------------------------------------------
// PTX helpers
// ---------------------------------------------------------------------------
__device__ __forceinline__ uint32_t smem_u32(const void* p) {
    uint32_t a;
    asm("{ .reg .u64 t; cvta.to.shared.u64 t, %1; cvt.u32.u64 %0, t; }" : "=r"(a) : "l"(p));
    return a;
}

#define CP16(dst, src, sz) \
    asm volatile("cp.async.cg.shared.global [%0], [%1], 16, %2;" \
                 :: "r"(dst), "l"(src), "r"(sz))
#define CP_COMMIT() asm volatile("cp.async.commit_group;" ::: "memory")
#define CP_WAIT2()  asm volatile("cp.async.wait_group 2;" ::: "memory")

#define LDSM4(r0, r1, r2, r3, addr) \
    asm volatile("ldmatrix.sync.aligned.m8n8.x4.shared.b16 {%0,%1,%2,%3}, [%4];" \
                 : "=r"(r0), "=r"(r1), "=r"(r2), "=r"(r3) : "r"(addr))

#define MMA(d, a, b0, b1) \
    asm volatile("mma.sync.aligned.m16n8k16.row.col.f32.f16.f16.f32 " \
                 "{%0,%1,%2,%3}, {%4,%5,%6,%7}, {%8,%9}, {%0,%1,%2,%3};" \
                 : "+f"((d)[0]), "+f"((d)[1]), "+f"((d)[2]), "+f"((d)[3]) \
                 : "r"((a)[0]), "r"((a)[1]), "r"((a)[2]), "r"((a)[3]), \
                   "r"(b0), "r"(b1))

__device__ __forceinline__ uint32_t h2u(__half a, __half b) {
    __half2 t(a, b);
    return *reinterpret_cast<uint32_t*>(&t);
}
__device__ __forceinline__ void split1(float x, __half& h, __half& l) {
    h = __float2half_rn(x);
    l = __float2half_rn(x - __half2float(h));
}
__device__ __forceinline__ float silu(float g) {
    return g / (1.0f + expf(-g));
}

// ---------------------------------------------------------------------------
// device scratch
// ---------------------------------------------------------------------------
#define WELEMS (16ull * 2048 * 1408)
__device__ int   g_cnt[NEXP];
__device__ int   g_off[NEXP + 1];
__device__ int   g_tok[NEXP][NTOK];
__device__ float g_wt[NEXP][NTOK];
__device__ __half g_x_hi[(size_t)NTOK * DHID], g_x_lo[(size_t)NTOK * DHID];
__device__ __half g_wgT[WELEMS];            // [e][n(1408)][k(2048)] fp16
__device__ __half g_wuT[WELEMS];
__device__ __half g_wdT[WELEMS];            // [e][n(2048)][k(1408)] fp16
__device__ __half g_h_hi[(size_t)NASSIGN * INTER], g_h_lo[(size_t)NASSIGN * INTER];

// ---------------------------------------------------------------------------
// 0. zero output + counters
// ---------------------------------------------------------------------------
__global__ void zero_kernel(float* __restrict__ out, int n) {
    int i = blockIdx.x * blockDim.x + threadIdx.x;
    int stride = gridDim.x * blockDim.x;
    for (; i < n; i += stride) out[i] = 0.0f;
    if (blockIdx.x == 0 && threadIdx.x < NEXP) g_cnt[threadIdx.x] = 0;
}

// ---------------------------------------------------------------------------
// 1. router
// ---------------------------------------------------------------------------
__global__ __launch_bounds__(256) void router_kernel(
    const float* __restrict__ x, const float* __restrict__ gw) {
    int gwarp = (blockIdx.x * blockDim.x + threadIdx.x) >> 5;
    int lane  = threadIdx.x & 31;
    if (gwarp >= NTOK) return;
    const float* xr = x + (size_t)gwarp * DHID;

    float acc[NEXP];
#pragma unroll
    for (int e = 0; e < NEXP; ++e) acc[e] = 0.0f;
    for (int d = lane; d < DHID; d += 32) {
        float xv = xr[d];
#pragma unroll
        for (int e = 0; e < NEXP; ++e) acc[e] += xv * gw[e * DHID + d];
    }
#pragma unroll
    for (int e = 0; e < NEXP; ++e)
#pragma unroll
        for (int s = 16; s > 0; s >>= 1)
            acc[e] += __shfl_xor_sync(0xffffffffu, acc[e], s);
    if (lane == 0) {
        float m1 = acc[0]; int a1 = 0;
#pragma unroll
        for (int e = 1; e < NEXP; ++e)
            if (acc[e] > m1) { m1 = acc[e]; a1 = e; }
        float m2 = -INFINITY; int a2 = 0;
#pragma unroll
        for (int e = 0; e < NEXP; ++e)
            if (e != a1 && acc[e] > m2) { m2 = acc[e]; a2 = e; }
        float w1 = 1.0f / (1.0f + expf(m2 - m1));
        float w2 = 1.0f - w1;
        int i1 = atomicAdd(&g_cnt[a1], 1);
        g_tok[a1][i1] = gwarp; g_wt[a1][i1] = w1;
        int i2 = atomicAdd(&g_cnt[a2], 1);
        g_tok[a2][i2] = gwarp; g_wt[a2][i2] = w2;
    }
}

__global__ void offsets_kernel() {
    if (threadIdx.x == 0) {
        int o = 0;
        for (int e = 0; e < NEXP; ++e) { g_off[e] = o; o += g_cnt[e]; }
        g_off[NEXP] = o;
    }
}

// ---------------------------------------------------------------------------
// 2a. split x fp32 -> fp16 hi/lo planes
// ---------------------------------------------------------------------------
__global__ __launch_bounds__(256) void split_x_kernel(const float* __restrict__ x) {
    size_t i = ((size_t)blockIdx.x * blockDim.x + threadIdx.x) * 4;
    if (i >= (size_t)NTOK * DHID) return;
    float4 v = *(const float4*)(x + i);
    __half h0, h1, h2, h3, l0, l1, l2, l3;
    split1(v.x, h0, l0); split1(v.y, h1, l1);
    split1(v.z, h2, l2); split1(v.w, h3, l3);
    *(uint2*)(g_x_hi + i) = make_uint2(h2u(h0, h1), h2u(h2, h3));
    *(uint2*)(g_x_lo + i) = make_uint2(h2u(l0, l1), h2u(l2, l3));
}

// ---------------------------------------------------------------------------
// 2b. transpose [K,N] -> [N,K] per expert + fp32 -> fp16 (single plane)
// ---------------------------------------------------------------------------
__global__ __launch_bounds__(256) void transpose_h_kernel(
    const float* __restrict__ in, int which, int K, int N) {
    __shared__ float t[32][33];
    int e = blockIdx.z;
    const float* ine = in + (size_t)e * K * N;
    __half* oh = (which == 0) ? g_wgT : (which == 1) ? g_wuT : g_wdT;
    size_t ob = (size_t)e * K * N;
    int n0 = blockIdx.x * 32, k0 = blockIdx.y * 32;
    int tx = threadIdx.x, ty = threadIdx.y;    // 32 x 8
#pragma unroll
    for (int j = 0; j < 4; ++j)
        t[ty + j * 8][tx] = ine[(size_t)(k0 + ty + j * 8) * N + n0 + tx];
    __syncthreads();
#pragma unroll
    for (int j = 0; j < 4; ++j) {
        int n = n0 + ty + j * 8, k = k0 + tx;
        oh[ob + (size_t)n * K + k] = __float2half_rn(t[tx][ty + j * 8]);
    }
}

// ---------------------------------------------------------------------------
// 3. GEMM1: CTA 128(m) x 64(n), computes gate AND up, K=2048.
//    8 warps (4m x 2n), warp tile 32x32 per matrix. 2-term fp16 mma.
//    Epilogue: h = silu(g)*u -> fp16 hi/lo planes.
// ---------------------------------------------------------------------------
__global__ __launch_bounds__(256) void gemm1_mma(void) {
    int e   = blockIdx.z;
    int cnt = g_cnt[e];
    int m0  = blockIdx.y * 128;
    if (m0 >= cnt) return;
    int n0   = blockIdx.x * 64;
    int base = g_off[e];

    extern __shared__ char dynsm[];
    uint32_t raw = smem_u32(dynsm);
    uint32_t smA = (raw + 127u) & ~127u;

    int tid = threadIdx.x, wid = tid >> 5, lane = tid & 31;

    // ---- producer mapping ----
    // A: 128 rows, 2 threads/row, each 2 x 16B chunks per plane
    int arow = tid >> 1;
    int aco  = (tid & 1) * 16;
    bool avalid = (m0 + arow < cnt);
    int atok = avalid ? g_tok[e][m0 + arow] : 0;
    uint32_t asz = avalid ? 16u : 0u;
    const __half* axh = g_x_hi + (size_t)atok * DHID + aco;
    const __half* axl = g_x_lo + (size_t)atok * DHID + aco;
    uint32_t adsth = arow * 80 + aco * 2;

    // B: 64 rows, 4 threads/row, 1 x 16B chunk per matrix
    int brow = tid >> 2;
    int bco  = (tid & 3) * 8;
    size_t wbase = ((size_t)e * INTER + n0 + brow) * DHID + bco;
    const __half* bg_src = g_wgT + wbase;
    const __half* bu_src = g_wuT + wbase;
    uint32_t bdst = brow * 80 + bco * 2;

    // ---- consumer mapping ----
    int wm = (wid >> 1) * 32;
    int wn = (wid & 1) * 32;
    int arl = lane & 15;
    int acl = (lane >> 4) * 8;
    int bnl = (lane & 7) + ((lane >> 4) << 3);
    int bkl = ((lane >> 3) & 1) * 8;

    float gacc[2][4][4], uacc[2][4][4];
#pragma unroll
    for (int mb = 0; mb < 2; ++mb)
#pragma unroll
        for (int nb = 0; nb < 4; ++nb)
#pragma unroll
            for (int i = 0; i < 4; ++i) { gacc[mb][nb][i] = 0.f; uacc[mb][nb][i] = 0.f; }

    const int NST = DHID / KS;   // 64

    auto issue = [&](int s) {
        uint32_t st = smA + (s % NBUF) * G1_STAGE;
        int k0 = s * KS;
        CP16(st + G1_AH + adsth,      axh + k0,     asz);
        CP16(st + G1_AH + adsth + 16, axh + k0 + 8, asz);
        CP16(st + G1_AL + adsth,      axl + k0,     asz);
        CP16(st + G1_AL + adsth + 16, axl + k0 + 8, asz);
        CP16(st + G1_G + bdst, bg_src + k0, 16u);
        CP16(st + G1_U + bdst, bu_src + k0, 16u);
    };

    issue(0); CP_COMMIT();
    issue(1); CP_COMMIT();

    for (int s = 0; s < NST; ++s) {
        if (s + 2 < NST) issue(s + 2);
        CP_COMMIT();
        CP_WAIT2();
        __syncthreads();

        uint32_t st = smA + (s % NBUF) * G1_STAGE;
#pragma unroll
        for (int kk = 0; kk < 2; ++kk) {
            int kofs = kk * 16;
            uint32_t ah[2][4], al[2][4];
#pragma unroll
            for (int mb = 0; mb < 2; ++mb) {
                uint32_t ao = ((wm + mb * 16 + arl) * ASTRIDE + kofs + acl) * 2;
                LDSM4(ah[mb][0], ah[mb][1], ah[mb][2], ah[mb][3], st + G1_AH + ao);
                LDSM4(al[mb][0], al[mb][1], al[mb][2], al[mb][3], st + G1_AL + ao);
            }
            uint32_t bg[2][4], bu[2][4];
#pragma unroll
            for (int p = 0; p < 2; ++p) {
                uint32_t bo = ((wn + p * 16 + bnl) * ASTRIDE + kofs + bkl) * 2;
                LDSM4(bg[p][0], bg[p][1], bg[p][2], bg[p][3], st + G1_G + bo);
                LDSM4(bu[p][0], bu[p][1], bu[p][2], bu[p][3], st + G1_U + bo);
            }
#pragma unroll
            for (int mb = 0; mb < 2; ++mb)
#pragma unroll
                for (int nb = 0; nb < 4; ++nb) {
                    int p = nb >> 1, o = (nb & 1) * 2;
                    MMA(gacc[mb][nb], ah[mb], bg[p][o], bg[p][o + 1]);
                    MMA(gacc[mb][nb], al[mb], bg[p][o], bg[p][o + 1]);
                    MMA(uacc[mb][nb], ah[mb], bu[p][o], bu[p][o + 1]);
                    MMA(uacc[mb][nb], al[mb], bu[p][o], bu[p][o + 1]);
                }
        }
        __syncthreads();
    }

    // epilogue: h = silu(g)*u, split to fp16 hi/lo
#pragma unroll
    for (int mb = 0; mb < 2; ++mb) {
#pragma unroll
        for (int half = 0; half < 2; ++half) {
            int m = m0 + wm + mb * 16 + (lane >> 2) + half * 8;
            if (m < cnt) {
                __half* hh = g_h_hi + (size_t)(base + m) * INTER + n0;
                __half* hl = g_h_lo + (size_t)(base + m) * INTER + n0;
#pragma unroll
                for (int nb = 0; nb < 4; ++nb) {
                    int c = wn + nb * 8 + (lane & 3) * 2;
                    float g0 = gacc[mb][nb][half * 2],     g1 = gacc[mb][nb][half * 2 + 1];
                    float u0 = uacc[mb][nb][half * 2],     u1 = uacc[mb][nb][half * 2 + 1];
                    float h0 = silu(g0) * u0, h1 = silu(g1) * u1;
                    __half a0, b0, a1, b1;
                    split1(h0, a0, b0); split1(h1, a1, b1);
                    *(uint32_t*)(hh + c) = h2u(a0, a1);
                    *(uint32_t*)(hl + c) = h2u(b0, b1);
                }
            }
        }
    }
}

// ---------------------------------------------------------------------------
// 4. GEMM2: CTA 128(m) x 128(n), K=1408. 8 warps (2m x 4n), warp tile 64x32.
//    2-term fp16 mma. Weighted atomicAdd scatter to out.
// ---------------------------------------------------------------------------
__global__ __launch_bounds__(256) void gemm2_mma(float* __restrict__ out) {
    int e   = blockIdx.z;
    int cnt = g_cnt[e];
    int m0  = blockIdx.y * 128;
    if (m0 >= cnt) return;
    int n0   = blockIdx.x * 128;
    int base = g_off[e];

    extern __shared__ char dynsm[];
    uint32_t raw = smem_u32(dynsm);
    uint32_t smA = (raw + 127u) & ~127u;

    int tid = threadIdx.x, wid = tid >> 5, lane = tid & 31;

    // producers: A 128 rows (2 thr/row, 2 chunks per plane); B 128 rows (single plane)
    int arow = tid >> 1;
    int aco  = (tid & 1) * 16;
    bool avalid = (m0 + arow < cnt);
    uint32_t asz = avalid ? 16u : 0u;
    size_t arix = (size_t)(base + (avalid ? m0 + arow : 0)) * INTER + aco;
    const __half* ahp = g_h_hi + arix;
    const __half* alp = g_h_lo + arix;
    uint32_t adst = arow * 80 + aco * 2;

    size_t wbase = ((size_t)e * DHID + n0 + arow) * INTER + aco;
    const __half* bp = g_wdT + wbase;

    // consumers
    int wm = (wid & 1) * 64;
    int wn = (wid >> 1) * 32;
    int arl = lane & 15, acl = (lane >> 4) * 8;
    int bnl = (lane & 7) + ((lane >> 4) << 3);
    int bkl = ((lane >> 3) & 1) * 8;

    float acc[4][4][4];
#pragma unroll
    for (int mb = 0; mb < 4; ++mb)
#pragma unroll
        for (int nb = 0; nb < 4; ++nb)
#pragma unroll
            for (int i = 0; i < 4; ++i) acc[mb][nb][i] = 0.f;

    const int NST = INTER / KS;  // 44

    auto issue = [&](int s) {
        uint32_t st = smA + (s % NBUF) * G2_STAGE;
        int k0 = s * KS;
        CP16(st + G2_AH + adst,      ahp + k0,     asz);
        CP16(st + G2_AH + adst + 16, ahp + k0 + 8, asz);
        CP16(st + G2_AL + adst,      alp + k0,     asz);
        CP16(st + G2_AL + adst + 16, alp + k0 + 8, asz);
        CP16(st + G2_B + adst,       bp + k0,      16u);
        CP16(st + G2_B + adst + 16,  bp + k0 + 8,  16u);
    };

    issue(0); CP_COMMIT();
    issue(1); CP_COMMIT();

    for (int s = 0; s < NST; ++s) {
        if (s + 2 < NST) issue(s + 2);
        CP_COMMIT();
        CP_WAIT2();
        __syncthreads();

        uint32_t st = smA + (s % NBUF) * G2_STAGE;
#pragma unroll
        for (int kk = 0; kk < 2; ++kk) {
            int kofs = kk * 16;
            uint32_t ah[4][4], al[4][4];
#pragma unroll
            for (int mb = 0; mb < 4; ++mb) {
                uint32_t ao = ((wm + mb * 16 + arl) * ASTRIDE + kofs + acl) * 2;
                LDSM4(ah[mb][0], ah[mb][1], ah[mb][2], ah[mb][3], st + G2_AH + ao);
                LDSM4(al[mb][0], al[mb][1], al[mb][2], al[mb][3], st + G2_AL + ao);
            }
            uint32_t bh[2][4];
#pragma unroll
            for (int p = 0; p < 2; ++p) {
                uint32_t bo = ((wn + p * 16 + bnl) * ASTRIDE + kofs + bkl) * 2;
                LDSM4(bh[p][0], bh[p][1], bh[p][2], bh[p][3], st + G2_B + bo);
            }
#pragma unroll
            for (int mb = 0; mb < 4; ++mb)
#pragma unroll
                for (int nb = 0; nb < 4; ++nb) {
                    int p = nb >> 1, o = (nb & 1) * 2;
                    MMA(acc[mb][nb], ah[mb], bh[p][o], bh[p][o + 1]);
                    MMA(acc[mb][nb], al[mb], bh[p][o], bh[p][o + 1]);
                }
        }
        __syncthreads();
    }

    // epilogue: weighted atomic scatter
#pragma unroll
    for (int mb = 0; mb < 4; ++mb) {
#pragma unroll
        for (int half = 0; half < 2; ++half) {
            int m = m0 + wm + mb * 16 + (lane >> 2) + half * 8;
            if (m < cnt) {
                int tok  = g_tok[e][m];
                float w  = g_wt[e][m];
                float* orow = out + (size_t)tok * DHID + n0;
#pragma unroll
                for (int nb = 0; nb < 4; ++nb) {
                    int c = wn + nb * 8 + (lane & 3) * 2;
                    atomicAdd(&orow[c],     w * acc[mb][nb][half * 2]);
                    atomicAdd(&orow[c + 1], w * acc[mb][nb][half * 2 + 1]);
                }
            }
        }
    }
}

// ---------------------------------------------------------------------------
extern "C" void kernel_launch(void* const* d_in, const int* in_sizes, int n_in,
                              void* d_out, int out_size) {
    const float* x  = (const float*)d_in[0];
    const float* gw = (const float*)d_in[1];
    const float* wg = (const float*)d_in[2];
    const float* wu = (const float*)d_in[3];
    const float* wd = (const float*)d_in[4];
    float* out = (float*)d_out;

    cudaFuncSetAttribute(gemm1_mma, cudaFuncAttributeMaxDynamicSharedMemorySize, SMEM_DYN);
    cudaFuncSetAttribute(gemm2_mma, cudaFuncAttributeMaxDynamicSharedMemorySize, SMEM_DYN);

    zero_kernel<<<2048, 256>>>(out, NTOK * DHID);
    router_kernel<<<NTOK / 8, 256>>>(x, gw);
    offsets_kernel<<<1, 32>>>();
    split_x_kernel<<<(NTOK * DHID / 4 + 255) / 256, 256>>>(x);
    transpose_h_kernel<<<dim3(INTER / 32, DHID / 32, NEXP), dim3(32, 8)>>>(wg, 0, DHID, INTER);
    transpose_h_kernel<<<dim3(INTER / 32, DHID / 32, NEXP), dim3(32, 8)>>>(wu, 1, DHID, INTER);
    transpose_h_kernel<<<dim3(DHID / 32, INTER / 32, NEXP), dim3(32, 8)>>>(wd, 2, INTER, DHID);
    gemm1_mma<<<dim3(INTER / 64, NTOK / 128, NEXP), 256, SMEM_DYN>>>();
    gemm2_mma<<<dim3(DHID / 128, NTOK / 128, NEXP), 256, SMEM_DYN>>>(out);
}

// round 10
// speedup vs baseline: 5.2930x; 1.6206x over previous
#include <cuda_runtime.h>
#include <cuda_fp16.h>
#include <stdint.h>
#include <math.h>

// ===========================================================================
// SparseMoeBlock, fp16 mma.sync 2-term split (A = hi+lo exact, B = fp16).
// R10: 128x128 / 128x256 CTA tiles, 4-deep cp.async pipeline w/ 1 barrier
// per stage, atomic-free gemm2 epilogue + combine kernel.
// ===========================================================================

#define DHID  2048
#define NEXP  16
#define INTER 1408
#define NTOK  8192
#define NASSIGN (NTOK * 2)

#define KS       32
#define ASTRIDE  40            // smem row stride in fp16 (80B)
#define NBUF     4

// gemm1 stage: Ah, Al (128x80B), G (128x80B), U (128x80B)
#define G1_AH 0
#define G1_AL 10240
#define G1_G  20480
#define G1_U  30720
// gemm2 stage: Ah, Al (128x80B), B (256x80B)
#define G2_AH 0
#define G2_AL 10240
#define G2_B  20480
#define STAGE_B 40960

#define SMEM_DYN (NBUF * STAGE_B + 128)

// ---------------------------------------------------------------------------
__device__ __forceinline__ uint32_t smem_u32(const void* p) {
    uint32_t a;
    asm("{ .reg .u64 t; cvta.to.shared.u64 t, %1; cvt.u32.u64 %0, t; }" : "=r"(a) : "l"(p));
    return a;
}
#define CP16(dst, src, sz) \
    asm volatile("cp.async.cg.shared.global [%0], [%1], 16, %2;" \
                 :: "r"(dst), "l"(src), "r"(sz))
#define CP_COMMIT() asm volatile("cp.async.commit_group;" ::: "memory")
#define CP_WAIT(n)  asm volatile("cp.async.wait_group %0;" :: "n"(n) : "memory")

#define LDSM4(r0, r1, r2, r3, addr) \
    asm volatile("ldmatrix.sync.aligned.m8n8.x4.shared.b16 {%0,%1,%2,%3}, [%4];" \
                 : "=r"(r0), "=r"(r1), "=r"(r2), "=r"(r3) : "r"(addr))

#define MMA(d, a, b0, b1) \
    asm volatile("mma.sync.aligned.m16n8k16.row.col.f32.f16.f16.f32 " \
                 "{%0,%1,%2,%3}, {%4,%5,%6,%7}, {%8,%9}, {%0,%1,%2,%3};" \
                 : "+f"((d)[0]), "+f"((d)[1]), "+f"((d)[2]), "+f"((d)[3]) \
                 : "r"((a)[0]), "r"((a)[1]), "r"((a)[2]), "r"((a)[3]), \
                   "r"(b0), "r"(b1))

__device__ __forceinline__ uint32_t h2u(__half a, __half b) {
    __half2 t(a, b);
    return *reinterpret_cast<uint32_t*>(&t);
}
__device__ __forceinline__ void split1(float x, __half& h, __half& l) {
    h = __float2half_rn(x);
    l = __float2half_rn(x - __half2float(h));
}
__device__ __forceinline__ float silu(float g) {
    return g / (1.0f + expf(-g));
}

// ---------------------------------------------------------------------------
// device scratch
// ---------------------------------------------------------------------------
#define WELEMS (16ull * 2048 * 1408)
__device__ int   g_cnt[NEXP];
__device__ int   g_off[NEXP + 1];
__device__ int   g_tok[NEXP][NTOK];
__device__ int   g_s_e[NTOK][2];
__device__ int   g_s_i[NTOK][2];
__device__ float g_s_w[NTOK][2];
__device__ __half g_x_hi[(size_t)NTOK * DHID], g_x_lo[(size_t)NTOK * DHID];
__device__ __half g_wgT[WELEMS];            // [e][n(1408)][k(2048)]
__device__ __half g_wuT[WELEMS];
__device__ __half g_wdT[WELEMS];            // [e][n(2048)][k(1408)]
__device__ __half g_h_hi[(size_t)NASSIGN * INTER], g_h_lo[(size_t)NASSIGN * INTER];
__device__ float  g_y[(size_t)NASSIGN * DHID];   // per-assignment down-proj output

// ---------------------------------------------------------------------------
__global__ void zero16_kernel() {
    if (threadIdx.x < NEXP) g_cnt[threadIdx.x] = 0;
}

// ---------------------------------------------------------------------------
__global__ __launch_bounds__(256) void router_kernel(
    const float* __restrict__ x, const float* __restrict__ gw) {
    int gwarp = (blockIdx.x * blockDim.x + threadIdx.x) >> 5;
    int lane  = threadIdx.x & 31;
    if (gwarp >= NTOK) return;
    const float* xr = x + (size_t)gwarp * DHID;

    float acc[NEXP];
#pragma unroll
    for (int e = 0; e < NEXP; ++e) acc[e] = 0.0f;
    for (int d = lane; d < DHID; d += 32) {
        float xv = xr[d];
#pragma unroll
        for (int e = 0; e < NEXP; ++e) acc[e] += xv * gw[e * DHID + d];
    }
#pragma unroll
    for (int e = 0; e < NEXP; ++e)
#pragma unroll
        for (int s = 16; s > 0; s >>= 1)
            acc[e] += __shfl_xor_sync(0xffffffffu, acc[e], s);
    if (lane == 0) {
        float m1 = acc[0]; int a1 = 0;
#pragma unroll
        for (int e = 1; e < NEXP; ++e)
            if (acc[e] > m1) { m1 = acc[e]; a1 = e; }
        float m2 = -INFINITY; int a2 = 0;
#pragma unroll
        for (int e = 0; e < NEXP; ++e)
            if (e != a1 && acc[e] > m2) { m2 = acc[e]; a2 = e; }
        float w1 = 1.0f / (1.0f + expf(m2 - m1));
        float w2 = 1.0f - w1;
        int i1 = atomicAdd(&g_cnt[a1], 1);
        g_tok[a1][i1] = gwarp;
        int i2 = atomicAdd(&g_cnt[a2], 1);
        g_tok[a2][i2] = gwarp;
        g_s_e[gwarp][0] = a1; g_s_i[gwarp][0] = i1; g_s_w[gwarp][0] = w1;
        g_s_e[gwarp][1] = a2; g_s_i[gwarp][1] = i2; g_s_w[gwarp][1] = w2;
    }
}

__global__ void offsets_kernel() {
    if (threadIdx.x == 0) {
        int o = 0;
        for (int e = 0; e < NEXP; ++e) { g_off[e] = o; o += g_cnt[e]; }
        g_off[NEXP] = o;
    }
}

// ---------------------------------------------------------------------------
__global__ __launch_bounds__(256) void split_x_kernel(const float* __restrict__ x) {
    size_t i = ((size_t)blockIdx.x * blockDim.x + threadIdx.x) * 4;
    if (i >= (size_t)NTOK * DHID) return;
    float4 v = *(const float4*)(x + i);
    __half h0, h1, h2, h3, l0, l1, l2, l3;
    split1(v.x, h0, l0); split1(v.y, h1, l1);
    split1(v.z, h2, l2); split1(v.w, h3, l3);
    *(uint2*)(g_x_hi + i) = make_uint2(h2u(h0, h1), h2u(h2, h3));
    *(uint2*)(g_x_lo + i) = make_uint2(h2u(l0, l1), h2u(l2, l3));
}

// ---------------------------------------------------------------------------
__global__ __launch_bounds__(256) void transpose_h_kernel(
    const float* __restrict__ in, int which, int K, int N) {
    __shared__ float t[32][33];
    int e = blockIdx.z;
    const float* ine = in + (size_t)e * K * N;
    __half* oh = (which == 0) ? g_wgT : (which == 1) ? g_wuT : g_wdT;
    size_t ob = (size_t)e * K * N;
    int n0 = blockIdx.x * 32, k0 = blockIdx.y * 32;
    int tx = threadIdx.x, ty = threadIdx.y;    // 32 x 8
#pragma unroll
    for (int j = 0; j < 4; ++j)
        t[ty + j * 8][tx] = ine[(size_t)(k0 + ty + j * 8) * N + n0 + tx];
    __syncthreads();
#pragma unroll
    for (int j = 0; j < 4; ++j) {
        int n = n0 + ty + j * 8, k = k0 + tx;
        oh[ob + (size_t)n * K + k] = __float2half_rn(t[tx][ty + j * 8]);
    }
}

// ---------------------------------------------------------------------------
// GEMM1: CTA 128(m) x 128(n), gate AND up, K=2048. 8 warps (2m x 4n),
// warp tile 64x32 per matrix. 2-term fp16 mma. 4-deep pipe, 1 barrier/stage.
// ---------------------------------------------------------------------------
__global__ __launch_bounds__(256, 1) void gemm1_mma(void) {
    int e   = blockIdx.z;
    int cnt = g_cnt[e];
    int m0  = blockIdx.y * 128;
    if (m0 >= cnt) return;
    int n0   = blockIdx.x * 128;
    int base = g_off[e];

    extern __shared__ char dynsm[];
    uint32_t raw = smem_u32(dynsm);
    uint32_t smA = (raw + 127u) & ~127u;

    int tid = threadIdx.x, wid = tid >> 5, lane = tid & 31;

    // producers: A 128 rows, 2 thr/row; B 128 rows, 2 thr/row, 2 mats
    int arow = tid >> 1;
    int aco  = (tid & 1) * 16;
    bool avalid = (m0 + arow < cnt);
    int atok = avalid ? g_tok[e][m0 + arow] : 0;
    uint32_t asz = avalid ? 16u : 0u;
    const __half* axh = g_x_hi + (size_t)atok * DHID + aco;
    const __half* axl = g_x_lo + (size_t)atok * DHID + aco;
    uint32_t adst = arow * 80 + aco * 2;

    size_t wbase = ((size_t)e * INTER + n0 + arow) * DHID + aco;
    const __half* bg_src = g_wgT + wbase;
    const __half* bu_src = g_wuT + wbase;

    // consumers: warp (2m x 4n), tile 64x32
    int wm = (wid >> 2) * 64;
    int wn = (wid & 3) * 32;
    int arl = lane & 15;
    int acl = (lane >> 4) * 8;
    int bnl = (lane & 7) + ((lane >> 4) << 3);
    int bkl = ((lane >> 3) & 1) * 8;

    float gacc[4][4][4], uacc[4][4][4];
#pragma unroll
    for (int mb = 0; mb < 4; ++mb)
#pragma unroll
        for (int nb = 0; nb < 4; ++nb)
#pragma unroll
            for (int i = 0; i < 4; ++i) { gacc[mb][nb][i] = 0.f; uacc[mb][nb][i] = 0.f; }

    const int NST = DHID / KS;   // 64

    auto issue = [&](int s) {
        uint32_t st = smA + (s & (NBUF - 1)) * STAGE_B;
        int k0 = s * KS;
        CP16(st + G1_AH + adst,      axh + k0,     asz);
        CP16(st + G1_AH + adst + 16, axh + k0 + 8, asz);
        CP16(st + G1_AL + adst,      axl + k0,     asz);
        CP16(st + G1_AL + adst + 16, axl + k0 + 8, asz);
        CP16(st + G1_G + adst,      bg_src + k0,     16u);
        CP16(st + G1_G + adst + 16, bg_src + k0 + 8, 16u);
        CP16(st + G1_U + adst,      bu_src + k0,     16u);
        CP16(st + G1_U + adst + 16, bu_src + k0 + 8, 16u);
    };

    issue(0); CP_COMMIT();
    issue(1); CP_COMMIT();
    issue(2); CP_COMMIT();

    for (int s = 0; s < NST; ++s) {
        CP_WAIT(2);
        __syncthreads();
        uint32_t st = smA + (s & (NBUF - 1)) * STAGE_B;
#pragma unroll
        for (int kk = 0; kk < 2; ++kk) {
            int kofs = kk * 16;
            uint32_t ah[4][4], al[4][4];
#pragma unroll
            for (int mb = 0; mb < 4; ++mb) {
                uint32_t ao = ((wm + mb * 16 + arl) * ASTRIDE + kofs + acl) * 2;
                LDSM4(ah[mb][0], ah[mb][1], ah[mb][2], ah[mb][3], st + G1_AH + ao);
                LDSM4(al[mb][0], al[mb][1], al[mb][2], al[mb][3], st + G1_AL + ao);
            }
            uint32_t bg[2][4], bu[2][4];
#pragma unroll
            for (int p = 0; p < 2; ++p) {
                uint32_t bo = ((wn + p * 16 + bnl) * ASTRIDE + kofs + bkl) * 2;
                LDSM4(bg[p][0], bg[p][1], bg[p][2], bg[p][3], st + G1_G + bo);
                LDSM4(bu[p][0], bu[p][1], bu[p][2], bu[p][3], st + G1_U + bo);
            }
#pragma unroll
            for (int mb = 0; mb < 4; ++mb)
#pragma unroll
                for (int nb = 0; nb < 4; ++nb) {
                    int p = nb >> 1, o = (nb & 1) * 2;
                    MMA(gacc[mb][nb], ah[mb], bg[p][o], bg[p][o + 1]);
                    MMA(gacc[mb][nb], al[mb], bg[p][o], bg[p][o + 1]);
                    MMA(uacc[mb][nb], ah[mb], bu[p][o], bu[p][o + 1]);
                    MMA(uacc[mb][nb], al[mb], bu[p][o], bu[p][o + 1]);
                }
        }
        if (s + 3 < NST) issue(s + 3);
        CP_COMMIT();
    }

    // epilogue: h = silu(g)*u -> fp16 hi/lo
#pragma unroll
    for (int mb = 0; mb < 4; ++mb) {
#pragma unroll
        for (int half = 0; half < 2; ++half) {
            int m = m0 + wm + mb * 16 + (lane >> 2) + half * 8;
            if (m < cnt) {
                __half* hh = g_h_hi + (size_t)(base + m) * INTER + n0;
                __half* hl = g_h_lo + (size_t)(base + m) * INTER + n0;
#pragma unroll
                for (int nb = 0; nb < 4; ++nb) {
                    int c = wn + nb * 8 + (lane & 3) * 2;
                    float g0 = gacc[mb][nb][half * 2],     g1 = gacc[mb][nb][half * 2 + 1];
                    float u0 = uacc[mb][nb][half * 2],     u1 = uacc[mb][nb][half * 2 + 1];
                    float h0 = silu(g0) * u0, h1 = silu(g1) * u1;
                    __half a0, b0, a1, b1;
                    split1(h0, a0, b0); split1(h1, a1, b1);
                    *(uint32_t*)(hh + c) = h2u(a0, a1);
                    *(uint32_t*)(hl + c) = h2u(b0, b1);
                }
            }
        }
    }
}

// ---------------------------------------------------------------------------
// GEMM2: CTA 128(m) x 256(n), K=1408. 8 warps (2m x 4n), warp tile 64x64.
// Writes unweighted y rows to g_y (no atomics).
// ---------------------------------------------------------------------------
__global__ __launch_bounds__(256, 1) void gemm2_mma(void) {
    int e   = blockIdx.z;
    int cnt = g_cnt[e];
    int m0  = blockIdx.y * 128;
    if (m0 >= cnt) return;
    int n0   = blockIdx.x * 256;
    int base = g_off[e];

    extern __shared__ char dynsm[];
    uint32_t raw = smem_u32(dynsm);
    uint32_t smA = (raw + 127u) & ~127u;

    int tid = threadIdx.x, wid = tid >> 5, lane = tid & 31;

    // producers: A 128 rows 2 thr/row; B 256 rows 1 thr/row (4 chunks)
    int arow = tid >> 1;
    int aco  = (tid & 1) * 16;
    bool avalid = (m0 + arow < cnt);
    uint32_t asz = avalid ? 16u : 0u;
    size_t arix = (size_t)(base + (avalid ? m0 + arow : 0)) * INTER + aco;
    const __half* ahp = g_h_hi + arix;
    const __half* alp = g_h_lo + arix;
    uint32_t adst = arow * 80 + aco * 2;

    const __half* bp = g_wdT + ((size_t)e * DHID + n0 + tid) * INTER;
    uint32_t bdst = tid * 80;

    // consumers: warp (2m x 4n), tile 64x64
    int wm = (wid >> 2) * 64;
    int wn = (wid & 3) * 64;
    int arl = lane & 15, acl = (lane >> 4) * 8;
    int bnl = (lane & 7) + ((lane >> 4) << 3);
    int bkl = ((lane >> 3) & 1) * 8;

    float acc[4][8][4];
#pragma unroll
    for (int mb = 0; mb < 4; ++mb)
#pragma unroll
        for (int nb = 0; nb < 8; ++nb)
#pragma unroll
            for (int i = 0; i < 4; ++i) acc[mb][nb][i] = 0.f;

    const int NST = INTER / KS;  // 44

    auto issue = [&](int s) {
        uint32_t st = smA + (s & (NBUF - 1)) * STAGE_B;
        int k0 = s * KS;
        CP16(st + G2_AH + adst,      ahp + k0,     asz);
        CP16(st + G2_AH + adst + 16, ahp + k0 + 8, asz);
        CP16(st + G2_AL + adst,      alp + k0,     asz);
        CP16(st + G2_AL + adst + 16, alp + k0 + 8, asz);
        CP16(st + G2_B + bdst,      bp + k0,      16u);
        CP16(st + G2_B + bdst + 16, bp + k0 + 8,  16u);
        CP16(st + G2_B + bdst + 32, bp + k0 + 16, 16u);
        CP16(st + G2_B + bdst + 48, bp + k0 + 24, 16u);
    };

    issue(0); CP_COMMIT();
    issue(1); CP_COMMIT();
    issue(2); CP_COMMIT();

    for (int s = 0; s < NST; ++s) {
        CP_WAIT(2);
        __syncthreads();
        uint32_t st = smA + (s & (NBUF - 1)) * STAGE_B;
#pragma unroll
        for (int kk = 0; kk < 2; ++kk) {
            int kofs = kk * 16;
            uint32_t ah[4][4], al[4][4];
#pragma unroll
            for (int mb = 0; mb < 4; ++mb) {
                uint32_t ao = ((wm + mb * 16 + arl) * ASTRIDE + kofs + acl) * 2;
                LDSM4(ah[mb][0], ah[mb][1], ah[mb][2], ah[mb][3], st + G2_AH + ao);
                LDSM4(al[mb][0], al[mb][1], al[mb][2], al[mb][3], st + G2_AL + ao);
            }
            uint32_t bh[4][4];
#pragma unroll
            for (int p = 0; p < 4; ++p) {
                uint32_t bo = ((wn + p * 16 + bnl) * ASTRIDE + kofs + bkl) * 2;
                LDSM4(bh[p][0], bh[p][1], bh[p][2], bh[p][3], st + G2_B + bo);
            }
#pragma unroll
            for (int mb = 0; mb < 4; ++mb)
#pragma unroll
                for (int nb = 0; nb < 8; ++nb) {
                    int p = nb >> 1, o = (nb & 1) * 2;
                    MMA(acc[mb][nb], ah[mb], bh[p][o], bh[p][o + 1]);
                    MMA(acc[mb][nb], al[mb], bh[p][o], bh[p][o + 1]);
                }
        }
        if (s + 3 < NST) issue(s + 3);
        CP_COMMIT();
    }

    // epilogue: plain stores to g_y (guard m < cnt to avoid cross-expert rows)
#pragma unroll
    for (int mb = 0; mb < 4; ++mb) {
#pragma unroll
        for (int half = 0; half < 2; ++half) {
            int m = m0 + wm + mb * 16 + (lane >> 2) + half * 8;
            if (m < cnt) {
                float* yrow = g_y + (size_t)(base + m) * DHID + n0;
#pragma unroll
                for (int nb = 0; nb < 8; ++nb) {
                    int c = wn + nb * 8 + (lane & 3) * 2;
                    float2 v = make_float2(acc[mb][nb][half * 2], acc[mb][nb][half * 2 + 1]);
                    *(float2*)(yrow + c) = v;
                }
            }
        }
    }
}

// ---------------------------------------------------------------------------
// Combine: out[t] = w0 * y[slot(t,0)] + w1 * y[slot(t,1)]   (writes all of out)
// ---------------------------------------------------------------------------
__global__ __launch_bounds__(256) void combine_kernel(float* __restrict__ out) {
    int t = blockIdx.x;
    int e0 = g_s_e[t][0], e1 = g_s_e[t][1];
    size_t s0 = (size_t)(g_off[e0] + g_s_i[t][0]) * DHID;
    size_t s1 = (size_t)(g_off[e1] + g_s_i[t][1]) * DHID;
    float w0 = g_s_w[t][0], w1 = g_s_w[t][1];
    size_t ob = (size_t)t * DHID;
#pragma unroll
    for (int r = 0; r < 2; ++r) {
        int c = (threadIdx.x + r * 256) * 4;
        float4 a = *(const float4*)(g_y + s0 + c);
        float4 b = *(const float4*)(g_y + s1 + c);
        float4 o;
        o.x = w0 * a.x + w1 * b.x;
        o.y = w0 * a.y + w1 * b.y;
        o.z = w0 * a.z + w1 * b.z;
        o.w = w0 * a.w + w1 * b.w;
        *(float4*)(out + ob + c) = o;
    }
}

// ---------------------------------------------------------------------------
extern "C" void kernel_launch(void* const* d_in, const int* in_sizes, int n_in,
                              void* d_out, int out_size) {
    const float* x  = (const float*)d_in[0];
    const float* gw = (const float*)d_in[1];
    const float* wg = (const float*)d_in[2];
    const float* wu = (const float*)d_in[3];
    const float* wd = (const float*)d_in[4];
    float* out = (float*)d_out;

    cudaFuncSetAttribute(gemm1_mma, cudaFuncAttributeMaxDynamicSharedMemorySize, SMEM_DYN);
    cudaFuncSetAttribute(gemm2_mma, cudaFuncAttributeMaxDynamicSharedMemorySize, SMEM_DYN);

    zero16_kernel<<<1, 32>>>();
    router_kernel<<<NTOK / 8, 256>>>(x, gw);
    offsets_kernel<<<1, 32>>>();
    split_x_kernel<<<(NTOK * DHID / 4 + 255) / 256, 256>>>(x);
    transpose_h_kernel<<<dim3(INTER / 32, DHID / 32, NEXP), dim3(32, 8)>>>(wg, 0, DHID, INTER);
    transpose_h_kernel<<<dim3(INTER / 32, DHID / 32, NEXP), dim3(32, 8)>>>(wu, 1, DHID, INTER);
    transpose_h_kernel<<<dim3(DHID / 32, INTER / 32, NEXP), dim3(32, 8)>>>(wd, 2, INTER, DHID);
    gemm1_mma<<<dim3(INTER / 128, NTOK / 128, NEXP), 256, SMEM_DYN>>>();
    gemm2_mma<<<dim3(DHID / 256, NTOK / 128, NEXP), 256, SMEM_DYN>>>();
    combine_kernel<<<NTOK, 256>>>(out);
}

// round 11
// speedup vs baseline: 7.6904x; 1.4529x over previous
#include <cuda_runtime.h>
#include <cuda_fp16.h>
#include <stdint.h>
#include <math.h>

// ===========================================================================
// SparseMoeBlock, fp16 mma.sync, SINGLE-term (A fp16 x B fp16, fp32 accum).
// Error budget ~5e-4 < 1e-3 (anchored on measured 2-term runs).
// 128x128 / 128x256 CTA tiles, 6-deep cp.async pipeline, 1 barrier/stage,
// atomic-free epilogue + combine.
// ===========================================================================

#define DHID  2048
#define NEXP  16
#define INTER 1408
#define NTOK  8192
#define NASSIGN (NTOK * 2)

#define KS       32
#define ASTRIDE  40            // smem row stride in fp16 (80B)
#define NBUF     6

// gemm1 stage: A (128x80B), G (128x80B), U (128x80B)
#define G1_A  0
#define G1_G  10240
#define G1_U  20480
// gemm2 stage: A (128x80B), B (256x80B)
#define G2_A  0
#define G2_B  10240
#define STAGE_B 30720

#define SMEM_DYN (NBUF * STAGE_B + 128)

// ---------------------------------------------------------------------------
__device__ __forceinline__ uint32_t smem_u32(const void* p) {
    uint32_t a;
    asm("{ .reg .u64 t; cvta.to.shared.u64 t, %1; cvt.u32.u64 %0, t; }" : "=r"(a) : "l"(p));
    return a;
}
#define CP16(dst, src, sz) \
    asm volatile("cp.async.cg.shared.global [%0], [%1], 16, %2;" \
                 :: "r"(dst), "l"(src), "r"(sz))
#define CP_COMMIT() asm volatile("cp.async.commit_group;" ::: "memory")
#define CP_WAIT(n)  asm volatile("cp.async.wait_group %0;" :: "n"(n) : "memory")

#define LDSM4(r0, r1, r2, r3, addr) \
    asm volatile("ldmatrix.sync.aligned.m8n8.x4.shared.b16 {%0,%1,%2,%3}, [%4];" \
                 : "=r"(r0), "=r"(r1), "=r"(r2), "=r"(r3) : "r"(addr))

#define MMA(d, a, b0, b1) \
    asm volatile("mma.sync.aligned.m16n8k16.row.col.f32.f16.f16.f32 " \
                 "{%0,%1,%2,%3}, {%4,%5,%6,%7}, {%8,%9}, {%0,%1,%2,%3};" \
                 : "+f"((d)[0]), "+f"((d)[1]), "+f"((d)[2]), "+f"((d)[3]) \
                 : "r"((a)[0]), "r"((a)[1]), "r"((a)[2]), "r"((a)[3]), \
                   "r"(b0), "r"(b1))

__device__ __forceinline__ uint32_t h2u(__half a, __half b) {
    __half2 t(a, b);
    return *reinterpret_cast<uint32_t*>(&t);
}
__device__ __forceinline__ float silu(float g) {
    return g / (1.0f + expf(-g));
}

// ---------------------------------------------------------------------------
// device scratch
// ---------------------------------------------------------------------------
#define WELEMS (16ull * 2048 * 1408)
__device__ int   g_cnt[NEXP];
__device__ int   g_off[NEXP + 1];
__device__ int   g_tok[NEXP][NTOK];
__device__ int   g_s_e[NTOK][2];
__device__ int   g_s_i[NTOK][2];
__device__ float g_s_w[NTOK][2];
__device__ __half g_x[(size_t)NTOK * DHID];
__device__ __half g_wgT[WELEMS];            // [e][n(1408)][k(2048)]
__device__ __half g_wuT[WELEMS];
__device__ __half g_wdT[WELEMS];            // [e][n(2048)][k(1408)]
__device__ __half g_h[(size_t)NASSIGN * INTER];
__device__ float  g_y[(size_t)NASSIGN * DHID];

// ---------------------------------------------------------------------------
__global__ void zero16_kernel() {
    if (threadIdx.x < NEXP) g_cnt[threadIdx.x] = 0;
}

// ---------------------------------------------------------------------------
__global__ __launch_bounds__(256) void router_kernel(
    const float* __restrict__ x, const float* __restrict__ gw) {
    int gwarp = (blockIdx.x * blockDim.x + threadIdx.x) >> 5;
    int lane  = threadIdx.x & 31;
    if (gwarp >= NTOK) return;
    const float* xr = x + (size_t)gwarp * DHID;

    float acc[NEXP];
#pragma unroll
    for (int e = 0; e < NEXP; ++e) acc[e] = 0.0f;
    for (int d = lane; d < DHID; d += 32) {
        float xv = xr[d];
#pragma unroll
        for (int e = 0; e < NEXP; ++e) acc[e] += xv * gw[e * DHID + d];
    }
#pragma unroll
    for (int e = 0; e < NEXP; ++e)
#pragma unroll
        for (int s = 16; s > 0; s >>= 1)
            acc[e] += __shfl_xor_sync(0xffffffffu, acc[e], s);
    if (lane == 0) {
        float m1 = acc[0]; int a1 = 0;
#pragma unroll
        for (int e = 1; e < NEXP; ++e)
            if (acc[e] > m1) { m1 = acc[e]; a1 = e; }
        float m2 = -INFINITY; int a2 = 0;
#pragma unroll
        for (int e = 0; e < NEXP; ++e)
            if (e != a1 && acc[e] > m2) { m2 = acc[e]; a2 = e; }
        float w1 = 1.0f / (1.0f + expf(m2 - m1));
        float w2 = 1.0f - w1;
        int i1 = atomicAdd(&g_cnt[a1], 1);
        g_tok[a1][i1] = gwarp;
        int i2 = atomicAdd(&g_cnt[a2], 1);
        g_tok[a2][i2] = gwarp;
        g_s_e[gwarp][0] = a1; g_s_i[gwarp][0] = i1; g_s_w[gwarp][0] = w1;
        g_s_e[gwarp][1] = a2; g_s_i[gwarp][1] = i2; g_s_w[gwarp][1] = w2;
    }
}

__global__ void offsets_kernel() {
    if (threadIdx.x == 0) {
        int o = 0;
        for (int e = 0; e < NEXP; ++e) { g_off[e] = o; o += g_cnt[e]; }
        g_off[NEXP] = o;
    }
}

// ---------------------------------------------------------------------------
__global__ __launch_bounds__(256) void convert_x_kernel(const float* __restrict__ x) {
    size_t i = ((size_t)blockIdx.x * blockDim.x + threadIdx.x) * 4;
    if (i >= (size_t)NTOK * DHID) return;
    float4 v = *(const float4*)(x + i);
    *(uint2*)(g_x + i) = make_uint2(
        h2u(__float2half_rn(v.x), __float2half_rn(v.y)),
        h2u(__float2half_rn(v.z), __float2half_rn(v.w)));
}

// ---------------------------------------------------------------------------
__global__ __launch_bounds__(256) void transpose_h_kernel(
    const float* __restrict__ in, int which, int K, int N) {
    __shared__ float t[32][33];
    int e = blockIdx.z;
    const float* ine = in + (size_t)e * K * N;
    __half* oh = (which == 0) ? g_wgT : (which == 1) ? g_wuT : g_wdT;
    size_t ob = (size_t)e * K * N;
    int n0 = blockIdx.x * 32, k0 = blockIdx.y * 32;
    int tx = threadIdx.x, ty = threadIdx.y;    // 32 x 8
#pragma unroll
    for (int j = 0; j < 4; ++j)
        t[ty + j * 8][tx] = ine[(size_t)(k0 + ty + j * 8) * N + n0 + tx];
    __syncthreads();
#pragma unroll
    for (int j = 0; j < 4; ++j) {
        int n = n0 + ty + j * 8, k = k0 + tx;
        oh[ob + (size_t)n * K + k] = __float2half_rn(t[tx][ty + j * 8]);
    }
}

// ---------------------------------------------------------------------------
// GEMM1: CTA 128(m) x 128(n), gate AND up, K=2048. 8 warps (2m x 4n),
// warp tile 64x32 per matrix. Single-term fp16 mma. 6-deep pipe.
// ---------------------------------------------------------------------------
__global__ __launch_bounds__(256, 1) void gemm1_mma(void) {
    int e   = blockIdx.z;
    int cnt = g_cnt[e];
    int m0  = blockIdx.y * 128;
    if (m0 >= cnt) return;
    int n0   = blockIdx.x * 128;
    int base = g_off[e];

    extern __shared__ char dynsm[];
    uint32_t raw = smem_u32(dynsm);
    uint32_t smA = (raw + 127u) & ~127u;

    int tid = threadIdx.x, wid = tid >> 5, lane = tid & 31;

    // producers: A 128 rows, 2 thr/row; G/U 128 rows, 2 thr/row
    int arow = tid >> 1;
    int aco  = (tid & 1) * 16;
    bool avalid = (m0 + arow < cnt);
    int atok = avalid ? g_tok[e][m0 + arow] : 0;
    uint32_t asz = avalid ? 16u : 0u;
    const __half* axp = g_x + (size_t)atok * DHID + aco;
    uint32_t adst = arow * 80 + aco * 2;

    size_t wbase = ((size_t)e * INTER + n0 + arow) * DHID + aco;
    const __half* bg_src = g_wgT + wbase;
    const __half* bu_src = g_wuT + wbase;

    // consumers: warp (2m x 4n), tile 64x32
    int wm = (wid >> 2) * 64;
    int wn = (wid & 3) * 32;
    int arl = lane & 15;
    int acl = (lane >> 4) * 8;
    int bnl = (lane & 7) + ((lane >> 4) << 3);
    int bkl = ((lane >> 3) & 1) * 8;

    float gacc[4][4][4], uacc[4][4][4];
#pragma unroll
    for (int mb = 0; mb < 4; ++mb)
#pragma unroll
        for (int nb = 0; nb < 4; ++nb)
#pragma unroll
            for (int i = 0; i < 4; ++i) { gacc[mb][nb][i] = 0.f; uacc[mb][nb][i] = 0.f; }

    const int NST = DHID / KS;   // 64

    auto issue = [&](int s) {
        uint32_t st = smA + (s % NBUF) * STAGE_B;
        int k0 = s * KS;
        CP16(st + G1_A + adst,      axp + k0,     asz);
        CP16(st + G1_A + adst + 16, axp + k0 + 8, asz);
        CP16(st + G1_G + adst,      bg_src + k0,     16u);
        CP16(st + G1_G + adst + 16, bg_src + k0 + 8, 16u);
        CP16(st + G1_U + adst,      bu_src + k0,     16u);
        CP16(st + G1_U + adst + 16, bu_src + k0 + 8, 16u);
    };

    issue(0); CP_COMMIT();
    issue(1); CP_COMMIT();
    issue(2); CP_COMMIT();
    issue(3); CP_COMMIT();
    issue(4); CP_COMMIT();

    for (int s = 0; s < NST; ++s) {
        CP_WAIT(4);
        __syncthreads();
        uint32_t st = smA + (s % NBUF) * STAGE_B;
#pragma unroll
        for (int kk = 0; kk < 2; ++kk) {
            int kofs = kk * 16;
            uint32_t ah[4][4];
#pragma unroll
            for (int mb = 0; mb < 4; ++mb) {
                uint32_t ao = ((wm + mb * 16 + arl) * ASTRIDE + kofs + acl) * 2;
                LDSM4(ah[mb][0], ah[mb][1], ah[mb][2], ah[mb][3], st + G1_A + ao);
            }
            uint32_t bg[2][4], bu[2][4];
#pragma unroll
            for (int p = 0; p < 2; ++p) {
                uint32_t bo = ((wn + p * 16 + bnl) * ASTRIDE + kofs + bkl) * 2;
                LDSM4(bg[p][0], bg[p][1], bg[p][2], bg[p][3], st + G1_G + bo);
                LDSM4(bu[p][0], bu[p][1], bu[p][2], bu[p][3], st + G1_U + bo);
            }
#pragma unroll
            for (int mb = 0; mb < 4; ++mb)
#pragma unroll
                for (int nb = 0; nb < 4; ++nb) {
                    int p = nb >> 1, o = (nb & 1) * 2;
                    MMA(gacc[mb][nb], ah[mb], bg[p][o], bg[p][o + 1]);
                    MMA(uacc[mb][nb], ah[mb], bu[p][o], bu[p][o + 1]);
                }
        }
        if (s + 5 < NST) issue(s + 5);
        CP_COMMIT();
    }

    // epilogue: h = silu(g)*u -> fp16
#pragma unroll
    for (int mb = 0; mb < 4; ++mb) {
#pragma unroll
        for (int half = 0; half < 2; ++half) {
            int m = m0 + wm + mb * 16 + (lane >> 2) + half * 8;
            if (m < cnt) {
                __half* hh = g_h + (size_t)(base + m) * INTER + n0;
#pragma unroll
                for (int nb = 0; nb < 4; ++nb) {
                    int c = wn + nb * 8 + (lane & 3) * 2;
                    float g0 = gacc[mb][nb][half * 2],     g1 = gacc[mb][nb][half * 2 + 1];
                    float u0 = uacc[mb][nb][half * 2],     u1 = uacc[mb][nb][half * 2 + 1];
                    float h0 = silu(g0) * u0, h1 = silu(g1) * u1;
                    *(uint32_t*)(hh + c) = h2u(__float2half_rn(h0), __float2half_rn(h1));
                }
            }
        }
    }
}

// ---------------------------------------------------------------------------
// GEMM2: CTA 128(m) x 256(n), K=1408. 8 warps (2m x 4n), warp tile 64x64.
// Single-term fp16 mma. Plain stores to g_y.
// ---------------------------------------------------------------------------
__global__ __launch_bounds__(256, 1) void gemm2_mma(void) {
    int e   = blockIdx.z;
    int cnt = g_cnt[e];
    int m0  = blockIdx.y * 128;
    if (m0 >= cnt) return;
    int n0   = blockIdx.x * 256;
    int base = g_off[e];

    extern __shared__ char dynsm[];
    uint32_t raw = smem_u32(dynsm);
    uint32_t smA = (raw + 127u) & ~127u;

    int tid = threadIdx.x, wid = tid >> 5, lane = tid & 31;

    // producers: A 128 rows 2 thr/row; B 256 rows 1 thr/row (4 chunks)
    int arow = tid >> 1;
    int aco  = (tid & 1) * 16;
    bool avalid = (m0 + arow < cnt);
    uint32_t asz = avalid ? 16u : 0u;
    const __half* ahp = g_h + (size_t)(base + (avalid ? m0 + arow : 0)) * INTER + aco;
    uint32_t adst = arow * 80 + aco * 2;

    const __half* bp = g_wdT + ((size_t)e * DHID + n0 + tid) * INTER;
    uint32_t bdst = tid * 80;

    // consumers: warp (2m x 4n), tile 64x64
    int wm = (wid >> 2) * 64;
    int wn = (wid & 3) * 64;
    int arl = lane & 15, acl = (lane >> 4) * 8;
    int bnl = (lane & 7) + ((lane >> 4) << 3);
    int bkl = ((lane >> 3) & 1) * 8;

    float acc[4][8][4];
#pragma unroll
    for (int mb = 0; mb < 4; ++mb)
#pragma unroll
        for (int nb = 0; nb < 8; ++nb)
#pragma unroll
            for (int i = 0; i < 4; ++i) acc[mb][nb][i] = 0.f;

    const int NST = INTER / KS;  // 44

    auto issue = [&](int s) {
        uint32_t st = smA + (s % NBUF) * STAGE_B;
        int k0 = s * KS;
        CP16(st + G2_A + adst,      ahp + k0,     asz);
        CP16(st + G2_A + adst + 16, ahp + k0 + 8, asz);
        CP16(st + G2_B + bdst,      bp + k0,      16u);
        CP16(st + G2_B + bdst + 16, bp + k0 + 8,  16u);
        CP16(st + G2_B + bdst + 32, bp + k0 + 16, 16u);
        CP16(st + G2_B + bdst + 48, bp + k0 + 24, 16u);
    };

    issue(0); CP_COMMIT();
    issue(1); CP_COMMIT();
    issue(2); CP_COMMIT();
    issue(3); CP_COMMIT();
    issue(4); CP_COMMIT();

    for (int s = 0; s < NST; ++s) {
        CP_WAIT(4);
        __syncthreads();
        uint32_t st = smA + (s % NBUF) * STAGE_B;
#pragma unroll
        for (int kk = 0; kk < 2; ++kk) {
            int kofs = kk * 16;
            uint32_t ah[4][4];
#pragma unroll
            for (int mb = 0; mb < 4; ++mb) {
                uint32_t ao = ((wm + mb * 16 + arl) * ASTRIDE + kofs + acl) * 2;
                LDSM4(ah[mb][0], ah[mb][1], ah[mb][2], ah[mb][3], st + G2_A + ao);
            }
            uint32_t bh[4][4];
#pragma unroll
            for (int p = 0; p < 4; ++p) {
                uint32_t bo = ((wn + p * 16 + bnl) * ASTRIDE + kofs + bkl) * 2;
                LDSM4(bh[p][0], bh[p][1], bh[p][2], bh[p][3], st + G2_B + bo);
            }
#pragma unroll
            for (int mb = 0; mb < 4; ++mb)
#pragma unroll
                for (int nb = 0; nb < 8; ++nb) {
                    int p = nb >> 1, o = (nb & 1) * 2;
                    MMA(acc[mb][nb], ah[mb], bh[p][o], bh[p][o + 1]);
                }
        }
        if (s + 5 < NST) issue(s + 5);
        CP_COMMIT();
    }

    // epilogue: plain stores to g_y
#pragma unroll
    for (int mb = 0; mb < 4; ++mb) {
#pragma unroll
        for (int half = 0; half < 2; ++half) {
            int m = m0 + wm + mb * 16 + (lane >> 2) + half * 8;
            if (m < cnt) {
                float* yrow = g_y + (size_t)(base + m) * DHID + n0;
#pragma unroll
                for (int nb = 0; nb < 8; ++nb) {
                    int c = wn + nb * 8 + (lane & 3) * 2;
                    float2 v = make_float2(acc[mb][nb][half * 2], acc[mb][nb][half * 2 + 1]);
                    *(float2*)(yrow + c) = v;
                }
            }
        }
    }
}

// ---------------------------------------------------------------------------
// Combine: out[t] = w0 * y[slot(t,0)] + w1 * y[slot(t,1)]
// ---------------------------------------------------------------------------
__global__ __launch_bounds__(256) void combine_kernel(float* __restrict__ out) {
    int t = blockIdx.x;
    int e0 = g_s_e[t][0], e1 = g_s_e[t][1];
    size_t s0 = (size_t)(g_off[e0] + g_s_i[t][0]) * DHID;
    size_t s1 = (size_t)(g_off[e1] + g_s_i[t][1]) * DHID;
    float w0 = g_s_w[t][0], w1 = g_s_w[t][1];
    size_t ob = (size_t)t * DHID;
#pragma unroll
    for (int r = 0; r < 2; ++r) {
        int c = (threadIdx.x + r * 256) * 4;
        float4 a = *(const float4*)(g_y + s0 + c);
        float4 b = *(const float4*)(g_y + s1 + c);
        float4 o;
        o.x = w0 * a.x + w1 * b.x;
        o.y = w0 * a.y + w1 * b.y;
        o.z = w0 * a.z + w1 * b.z;
        o.w = w0 * a.w + w1 * b.w;
        *(float4*)(out + ob + c) = o;
    }
}

// ---------------------------------------------------------------------------
extern "C" void kernel_launch(void* const* d_in, const int* in_sizes, int n_in,
                              void* d_out, int out_size) {
    const float* x  = (const float*)d_in[0];
    const float* gw = (const float*)d_in[1];
    const float* wg = (const float*)d_in[2];
    const float* wu = (const float*)d_in[3];
    const float* wd = (const float*)d_in[4];
    float* out = (float*)d_out;

    cudaFuncSetAttribute(gemm1_mma, cudaFuncAttributeMaxDynamicSharedMemorySize, SMEM_DYN);
    cudaFuncSetAttribute(gemm2_mma, cudaFuncAttributeMaxDynamicSharedMemorySize, SMEM_DYN);

    zero16_kernel<<<1, 32>>>();
    router_kernel<<<NTOK / 8, 256>>>(x, gw);
    offsets_kernel<<<1, 32>>>();
    convert_x_kernel<<<(NTOK * DHID / 4 + 255) / 256, 256>>>(x);
    transpose_h_kernel<<<dim3(INTER / 32, DHID / 32, NEXP), dim3(32, 8)>>>(wg, 0, DHID, INTER);
    transpose_h_kernel<<<dim3(INTER / 32, DHID / 32, NEXP), dim3(32, 8)>>>(wu, 1, DHID, INTER);
    transpose_h_kernel<<<dim3(DHID / 32, INTER / 32, NEXP), dim3(32, 8)>>>(wd, 2, INTER, DHID);
    gemm1_mma<<<dim3(INTER / 128, NTOK / 128, NEXP), 256, SMEM_DYN>>>();
    gemm2_mma<<<dim3(DHID / 256, NTOK / 128, NEXP), 256, SMEM_DYN>>>();
    combine_kernel<<<NTOK, 256>>>(out);
}